// round 1
// baseline (speedup 1.0000x reference)
#include <cuda_runtime.h>

namespace {
constexpr int T_STEPS = 256;
constexpr int B_SZ    = 4096;
constexpr int HID     = 64;
constexpr int MLPW    = 128;
constexpr int DOUT    = 8;
constexpr int R_ROWS  = 4;    // batch rows per warp
constexpr int NWARPS  = 8;    // warps per CTA
constexpr int NSTEP   = 255;
constexpr int ROWS_PER_CTA = R_ROWS * NWARPS;   // 32
constexpr int NCTA = B_SZ / ROWS_PER_CTA;       // 128
}

__device__ __forceinline__ float4 ldg4(const float* p) {
    return __ldg(reinterpret_cast<const float4*>(p));
}
__device__ __forceinline__ float2 ldg2(const float* p) {
    return __ldg(reinterpret_cast<const float2*>(p));
}
__device__ __forceinline__ float lipswish(float x) {
    float s = 1.0f / (1.0f + __expf(-x));
    return 0.909f * x * s;
}
__device__ __forceinline__ float f4c(const float4& v, int kk) {
    return kk == 0 ? v.x : kk == 1 ? v.y : kk == 2 ? v.z : v.w;
}

// acc[R][4] += src(R x K) * W(K x 128), lane owns columns 4*lane..4*lane+3
template<int K, int SSTRIDE>
__device__ __forceinline__ void gemm_n128(const float* __restrict__ W,
                                          const float* __restrict__ src,
                                          float acc[R_ROWS][4], int lane)
{
    const float* Wp = W + 4 * lane;
#pragma unroll 4
    for (int kb = 0; kb < K / 4; kb++) {
        float4 a[R_ROWS];
#pragma unroll
        for (int r = 0; r < R_ROWS; r++)
            a[r] = *reinterpret_cast<const float4*>(src + r * SSTRIDE + kb * 4);
        float4 wv[4];
#pragma unroll
        for (int kk = 0; kk < 4; kk++)
            wv[kk] = ldg4(Wp + (kb * 4 + kk) * MLPW);
#pragma unroll
        for (int r = 0; r < R_ROWS; r++) {
#pragma unroll
            for (int kk = 0; kk < 4; kk++) {
                float av = f4c(a[r], kk);
                acc[r][0] = fmaf(av, wv[kk].x, acc[r][0]);
                acc[r][1] = fmaf(av, wv[kk].y, acc[r][1]);
                acc[r][2] = fmaf(av, wv[kk].z, acc[r][2]);
                acc[r][3] = fmaf(av, wv[kk].w, acc[r][3]);
            }
        }
    }
}

// acc[R][2] += src(R x K) * W(K x 64), lane owns columns 2*lane..2*lane+1
template<int K, int SSTRIDE>
__device__ __forceinline__ void gemm_n64(const float* __restrict__ W,
                                         const float* __restrict__ src,
                                         float acc[R_ROWS][2], int lane)
{
    const float* Wp = W + 2 * lane;
#pragma unroll 4
    for (int kb = 0; kb < K / 4; kb++) {
        float4 a[R_ROWS];
#pragma unroll
        for (int r = 0; r < R_ROWS; r++)
            a[r] = *reinterpret_cast<const float4*>(src + r * SSTRIDE + kb * 4);
        float2 wv[4];
#pragma unroll
        for (int kk = 0; kk < 4; kk++)
            wv[kk] = ldg2(Wp + (kb * 4 + kk) * HID);
#pragma unroll
        for (int r = 0; r < R_ROWS; r++) {
#pragma unroll
            for (int kk = 0; kk < 4; kk++) {
                float av = f4c(a[r], kk);
                acc[r][0] = fmaf(av, wv[kk].x, acc[r][0]);
                acc[r][1] = fmaf(av, wv[kk].y, acc[r][1]);
            }
        }
    }
}

// One full MLP: tx = [t, x(64)] -> lipswish -> lipswish -> tanh. Output in
// outv[r][s] for hidden index h = 2*lane + s (matches the state register layout).
__device__ __forceinline__ void mlp_eval(
    float tn,
    const float* __restrict__ W0, const float* __restrict__ b0,
    const float* __restrict__ W1, const float* __restrict__ b1,
    const float* __restrict__ Wo, const float* __restrict__ bo,
    const float* __restrict__ sIn,   // [R_ROWS][HID]  (x part of tx)
    float* __restrict__ sH1,         // [R_ROWS][MLPW]
    float* __restrict__ sH2,         // [R_ROWS][MLPW]
    float outv[R_ROWS][2], int lane)
{
    float acc[R_ROWS][4];
    {   // bias + t * W0_row0 (tx[0] = t is uniform across rows and lanes)
        float4 bv = ldg4(b0 + 4 * lane);
        float4 w0 = ldg4(W0 + 4 * lane);
#pragma unroll
        for (int r = 0; r < R_ROWS; r++) {
            acc[r][0] = fmaf(tn, w0.x, bv.x);
            acc[r][1] = fmaf(tn, w0.y, bv.y);
            acc[r][2] = fmaf(tn, w0.z, bv.z);
            acc[r][3] = fmaf(tn, w0.w, bv.w);
        }
    }
    gemm_n128<HID, HID>(W0 + MLPW, sIn, acc, lane);   // rows 1..64 of W0
#pragma unroll
    for (int r = 0; r < R_ROWS; r++) {
        float4 o;
        o.x = lipswish(acc[r][0]); o.y = lipswish(acc[r][1]);
        o.z = lipswish(acc[r][2]); o.w = lipswish(acc[r][3]);
        *reinterpret_cast<float4*>(sH1 + r * MLPW + 4 * lane) = o;
    }
    __syncwarp();

    {
        float4 bv = ldg4(b1 + 4 * lane);
#pragma unroll
        for (int r = 0; r < R_ROWS; r++) {
            acc[r][0] = bv.x; acc[r][1] = bv.y; acc[r][2] = bv.z; acc[r][3] = bv.w;
        }
    }
    gemm_n128<MLPW, MLPW>(W1, sH1, acc, lane);
#pragma unroll
    for (int r = 0; r < R_ROWS; r++) {
        float4 o;
        o.x = lipswish(acc[r][0]); o.y = lipswish(acc[r][1]);
        o.z = lipswish(acc[r][2]); o.w = lipswish(acc[r][3]);
        *reinterpret_cast<float4*>(sH2 + r * MLPW + 4 * lane) = o;
    }
    __syncwarp();

    float acc2[R_ROWS][2];
    {
        float2 bv = ldg2(bo + 2 * lane);
#pragma unroll
        for (int r = 0; r < R_ROWS; r++) { acc2[r][0] = bv.x; acc2[r][1] = bv.y; }
    }
    gemm_n64<MLPW, MLPW>(Wo, sH2, acc2, lane);
#pragma unroll
    for (int r = 0; r < R_ROWS; r++) {
        outv[r][0] = tanhf(acc2[r][0]);
        outv[r][1] = tanhf(acc2[r][1]);
    }
}

// lane (r = lane>>3, d = lane&7): ys[r][d] = rb[d] + z[r,:] @ RW[:,d]
__device__ __forceinline__ void readout_store(
    const float* __restrict__ myZ,          // [R_ROWS][HID] holds z
    const float (*sRWt)[68], const float* __restrict__ sRB,
    float* __restrict__ out, int rowbase, int tIdx, float tval, int lane)
{
    const int r = lane >> 3;
    const int d = lane & 7;
    float acc = sRB[d];
#pragma unroll
    for (int hb = 0; hb < HID / 4; hb++) {
        float4 zv = *reinterpret_cast<const float4*>(myZ + r * HID + hb * 4);
        float4 wv = *reinterpret_cast<const float4*>(&sRWt[d][hb * 4]);
        acc = fmaf(zv.x, wv.x, acc);
        acc = fmaf(zv.y, wv.y, acc);
        acc = fmaf(zv.z, wv.z, acc);
        acc = fmaf(zv.w, wv.w, acc);
    }
    size_t base = ((size_t)(rowbase + r) * T_STEPS + tIdx) * (DOUT + 1);
    out[base + 1 + d] = acc;
    if (d == 0) out[base] = tval;
}

__global__ void __launch_bounds__(NWARPS * 32, 1)
sde_kernel(const float* __restrict__ ts,
           const float* __restrict__ dW,
           const float* __restrict__ dW0, const float* __restrict__ db0,
           const float* __restrict__ dW1, const float* __restrict__ db1,
           const float* __restrict__ dWo, const float* __restrict__ dbo,
           const float* __restrict__ fW0, const float* __restrict__ fb0,
           const float* __restrict__ fW1, const float* __restrict__ fb1,
           const float* __restrict__ fWo, const float* __restrict__ fbo,
           const float* __restrict__ RW, const float* __restrict__ rb,
           float* __restrict__ out)
{
    __shared__ float sZ [NWARPS][R_ROWS][HID];   // 8 KB  (x / zhat / z staging)
    __shared__ float sH1[NWARPS][R_ROWS][MLPW];  // 16 KB
    __shared__ float sH2[NWARPS][R_ROWS][MLPW];  // 16 KB
    __shared__ float sRWt[DOUT][68];             // readout W, transposed + padded
    __shared__ float sRB[DOUT];

    const int tid  = threadIdx.x;
    const int w    = tid >> 5;
    const int lane = tid & 31;

    for (int i = tid; i < HID * DOUT; i += blockDim.x)
        sRWt[i & 7][i >> 3] = __ldg(RW + i);     // RW is (64, 8) row-major
    if (tid < DOUT) sRB[tid] = __ldg(rb + tid);
    __syncthreads();

    const int rowbase = (blockIdx.x * NWARPS + w) * R_ROWS;
    const float t0  = __ldg(ts + 0);
    const float dt  = __ldg(ts + 1) - t0;
    const float sdt = sqrtf(dt);

    float z[R_ROWS][2], zh[R_ROWS][2], f[R_ROWS][2], g[R_ROWS][2], dwc[R_ROWS][2];

    float* myZ  = &sZ[w][0][0];
    float* myH1 = &sH1[w][0][0];
    float* myH2 = &sH2[w][0][0];

#pragma unroll
    for (int r = 0; r < R_ROWS; r++) {
        z[r][0] = z[r][1] = 1.0f;
        zh[r][0] = zh[r][1] = 1.0f;
        *reinterpret_cast<float2*>(myZ + r * HID + 2 * lane) = make_float2(1.0f, 1.0f);
    }
    __syncwarp();

    // f0, g0 at t = ts[0], x0 = ones
    mlp_eval(t0, dW0, db0, dW1, db1, dWo, dbo, myZ, myH1, myH2, f, lane);
    mlp_eval(t0, fW0, fb0, fW1, fb1, fWo, fbo, myZ, myH1, myH2, g, lane);

    // t = 0 output (myZ still holds x0 = ones)
    readout_store(myZ, sRWt, sRB, out, rowbase, 0, t0, lane);

    // Brownian increments for step 0 (pre-scaled by sqrt(dt))
#pragma unroll
    for (int r = 0; r < R_ROWS; r++) {
        float2 v = ldg2(dW + (size_t)(rowbase + r) * HID + 2 * lane);
        dwc[r][0] = v.x * sdt; dwc[r][1] = v.y * sdt;
    }
    __syncwarp();

    for (int n = 0; n < NSTEP; n++) {
        const float tn = __ldg(ts + n + 1);

        // zhat_{n+1} = 2 z - zhat + f dt + g dw ; stage into shared for the MLPs
#pragma unroll
        for (int r = 0; r < R_ROWS; r++) {
#pragma unroll
            for (int s = 0; s < 2; s++)
                zh[r][s] = 2.0f * z[r][s] - zh[r][s] + f[r][s] * dt + g[r][s] * dwc[r][s];
            *reinterpret_cast<float2*>(myZ + r * HID + 2 * lane) =
                make_float2(zh[r][0], zh[r][1]);
        }
        __syncwarp();

        float fn[R_ROWS][2], gn[R_ROWS][2];
        mlp_eval(tn, dW0, db0, dW1, db1, dWo, dbo, myZ, myH1, myH2, fn, lane);
        mlp_eval(tn, fW0, fb0, fW1, fb1, fWo, fbo, myZ, myH1, myH2, gn, lane);

        // z_{n+1} = z + 0.5 (f + fn) dt + 0.5 (g + gn) dw
#pragma unroll
        for (int r = 0; r < R_ROWS; r++) {
#pragma unroll
            for (int s = 0; s < 2; s++) {
                z[r][s] += 0.5f * (f[r][s] + fn[r][s]) * dt
                         + 0.5f * (g[r][s] + gn[r][s]) * dwc[r][s];
                f[r][s] = fn[r][s];
                g[r][s] = gn[r][s];
            }
        }

        // prefetch next step's dW while the readout below runs
        if (n + 1 < NSTEP) {
#pragma unroll
            for (int r = 0; r < R_ROWS; r++) {
                float2 v = ldg2(dW + ((size_t)(n + 1) * B_SZ + (rowbase + r)) * HID + 2 * lane);
                dwc[r][0] = v.x * sdt; dwc[r][1] = v.y * sdt;
            }
        }

        __syncwarp();
#pragma unroll
        for (int r = 0; r < R_ROWS; r++)
            *reinterpret_cast<float2*>(myZ + r * HID + 2 * lane) =
                make_float2(z[r][0], z[r][1]);
        __syncwarp();

        readout_store(myZ, sRWt, sRB, out, rowbase, n + 1, tn, lane);
        __syncwarp();
    }
}

extern "C" void kernel_launch(void* const* d_in, const int* in_sizes, int n_in,
                              void* d_out, int out_size) {
    (void)in_sizes; (void)n_in; (void)out_size;
    const float* ts  = (const float*)d_in[0];
    // d_in[1] = batch_size (int32 scalar) — shapes are fixed constants here
    const float* dW  = (const float*)d_in[2];
    const float* dW0 = (const float*)d_in[3];
    const float* db0 = (const float*)d_in[4];
    const float* dW1 = (const float*)d_in[5];
    const float* db1 = (const float*)d_in[6];
    const float* dWo = (const float*)d_in[7];
    const float* dbo = (const float*)d_in[8];
    const float* fW0 = (const float*)d_in[9];
    const float* fb0 = (const float*)d_in[10];
    const float* fW1 = (const float*)d_in[11];
    const float* fb1 = (const float*)d_in[12];
    const float* fWo = (const float*)d_in[13];
    const float* fbo = (const float*)d_in[14];
    const float* RW  = (const float*)d_in[15];
    const float* rb  = (const float*)d_in[16];
    float* out = (float*)d_out;

    sde_kernel<<<NCTA, NWARPS * 32>>>(ts, dW,
                                      dW0, db0, dW1, db1, dWo, dbo,
                                      fW0, fb0, fW1, fb1, fWo, fbo,
                                      RW, rb, out);
}